// round 3
// baseline (speedup 1.0000x reference)
#include <cuda_runtime.h>
#include <stdint.h>

#define BB 32
#define AA 65536
#define CC 21
#define NANCH (BB*AA)
#define MAIN_BLOCKS (NANCH/256)
#define STH 1024              // threads in select_k
#define SV4 (AA/4/STH)        // float4 elements per thread per pass = 16

// ---------------- scratch (device globals; no allocation allowed) ----------
__device__ float        g_neg[NANCH];       // neg_cand per anchor (8 MB, L2-resident)
__device__ unsigned int g_hist[BB*256];     // per-row level-0 histogram (zeroed by select_k)
__device__ int          g_numpos[BB];
__device__ double       g_locsum;           // global smooth-L1 sum over positives
__device__ double       g_posce;            // global CE sum over positives
__device__ double       g_negsum;           // accumulated hard-negative sum
__device__ unsigned int g_done;             // arrival ticket for final combine

// ---------------- helpers ---------------------------------------------------
__device__ __forceinline__ double blockReduceD256(double x, double* sred) {
    int lane = threadIdx.x & 31, wid = threadIdx.x >> 5;
#pragma unroll
    for (int o = 16; o; o >>= 1) x += __shfl_down_sync(0xffffffffu, x, o);
    if (lane == 0) sred[wid] = x;
    __syncthreads();
    double r = (wid == 0 && lane < 8) ? sred[lane] : 0.0;
    if (wid == 0) {
#pragma unroll
        for (int o = 4; o; o >>= 1) r += __shfl_down_sync(0xffffffffu, r, o);
    }
    return r;  // valid on thread 0
}

__device__ __forceinline__ double blockReduceD1024(double x, double* sred) {
    int lane = threadIdx.x & 31, wid = threadIdx.x >> 5;
#pragma unroll
    for (int o = 16; o; o >>= 1) x += __shfl_down_sync(0xffffffffu, x, o);
    if (lane == 0) sred[wid] = x;
    __syncthreads();
    double r = (wid == 0) ? sred[lane] : 0.0;
    if (wid == 0) {
#pragma unroll
        for (int o = 16; o; o >>= 1) r += __shfl_down_sync(0xffffffffu, r, o);
    }
    return r;  // valid on thread 0
}

// ---------------- main kernel ------------------------------------------------
__global__ void __launch_bounds__(256) main_k(const float* __restrict__ locp,
                                              const float* __restrict__ loct,
                                              const float* __restrict__ cls,
                                              const int* __restrict__ tgt) {
    __shared__ float        scls[256*CC];   // 21504 B
    __shared__ unsigned int shist[256];
    __shared__ double       sred[8];

    const int tid    = threadIdx.x;
    const int anchor = blockIdx.x * 256 + tid;
    const int row    = anchor >> 16;

    // stage cls tile (coalesced float4)
    {
        const float4* src = reinterpret_cast<const float4*>(cls) + (size_t)blockIdx.x * (256*CC/4);
        float4*       dst = reinterpret_cast<float4*>(scls);
#pragma unroll
        for (int i = 0; i < 6; i++) {
            int idx = tid + i * 256;
            if (idx < 256*CC/4) dst[idx] = src[idx];
        }
    }
    shist[tid] = 0u;
    __syncthreads();

    int  t   = tgt[anchor];
    bool pos = (t > 0);

    // logsumexp over 21 classes from shared (stride-21 is bank-conflict-free)
    float v[CC];
#pragma unroll
    for (int c = 0; c < CC; c++) v[c] = scls[tid*CC + c];
    float m = v[0];
#pragma unroll
    for (int c = 1; c < CC; c++) m = fmaxf(m, v[c]);
    float s = 0.f;
#pragma unroll
    for (int c = 0; c < CC; c++) s += __expf(v[c] - m);

    int tc = t; tc = tc < 0 ? 0 : (tc > CC-1 ? CC-1 : tc);
    float picked = scls[tid*CC + tc];
    float ce     = (t == -1) ? 0.f : (m + __logf(s) - picked);
    float negc   = pos ? 0.f : ce;
    g_neg[anchor] = negc;

    // smooth-L1 (unconditional loads; result masked by pos)
    float4 p = reinterpret_cast<const float4*>(locp)[anchor];
    float4 q = reinterpret_cast<const float4*>(loct)[anchor];
    float d0 = p.x-q.x, d1 = p.y-q.y, d2 = p.z-q.z, d3 = p.w-q.w;
    float a0 = fabsf(d0), a1 = fabsf(d1), a2 = fabsf(d2), a3 = fabsf(d3);
    float lsum = (a0 < 1.f ? 0.5f*d0*d0 : a0-0.5f)
               + (a1 < 1.f ? 0.5f*d1*d1 : a1-0.5f)
               + (a2 < 1.f ? 0.5f*d2*d2 : a2-0.5f)
               + (a3 < 1.f ? 0.5f*d3*d3 : a3-0.5f);
    if (!pos) lsum = 0.f;

    // level-0 histogram of float bits (warp-aggregated; bin 0 is hot)
    {
        unsigned bits = __float_as_uint(negc);
        unsigned bin  = bits >> 24;
        unsigned mk   = __match_any_sync(0xffffffffu, bin);
        if ((tid & 31) == (__ffs(mk) - 1))
            atomicAdd(&shist[bin], (unsigned)__popc(mk));
    }

    int npos = __syncthreads_count(pos ? 1 : 0);   // barrier also orders shist

    double bl = blockReduceD256((double)lsum, sred);
    __syncthreads();
    double bp = blockReduceD256(pos ? (double)ce : 0.0, sred);

    if (tid == 0) {
        atomicAdd(&g_locsum, bl);
        atomicAdd(&g_posce,  bp);
        atomicAdd(&g_numpos[row], npos);
    }
    if (shist[tid]) atomicAdd(&g_hist[row*256 + tid], shist[tid]);
}

// ---------------- fused radix select + combine --------------------------------
// One block per batch row. Levels 1-3 of the 8-bit radix select over float bit
// patterns (values >= 0 so bit order is monotone), then sum of values > T, then
// a ticketed global combine. Last block writes the output and resets all state.
__global__ void __launch_bounds__(STH) select_k(float* __restrict__ out) {
    __shared__ unsigned  scnt[256];
    __shared__ unsigned  s_prefix;
    __shared__ long long s_krem;
    __shared__ double    sred[32];

    const int row = blockIdx.x;
    const int tid = threadIdx.x;

    // ---- level 0: consume g_hist (and zero it for next replay) ----
    if (tid < 256) {
        scnt[tid] = g_hist[row*256 + tid];
        g_hist[row*256 + tid] = 0u;
    }
    __syncthreads();
    if (tid == 0) {
        long long k = 3LL * (long long)g_numpos[row];
        if (k < 1) k = 1;
        if (k > AA-1) k = AA-1;
        long long above = 0; int d = 255;
        for (; d > 0; --d) {
            if (above + (long long)scnt[d] >= k) break;
            above += (long long)scnt[d];
        }
        s_krem = k - above;
        s_prefix = (unsigned)d;
    }
    __syncthreads();

    const float4* base4 = reinterpret_cast<const float4*>(g_neg + (size_t)row*AA);

    // ---- levels 1..3 ----
#pragma unroll
    for (int shift = 16; shift >= 0; shift -= 8) {
        unsigned pfx = s_prefix;
        if (tid < 256) scnt[tid] = 0u;
        __syncthreads();
#pragma unroll 4
        for (int i = 0; i < SV4; i++) {
            float4 v = base4[tid + i*STH];
            unsigned b[4] = { __float_as_uint(v.x), __float_as_uint(v.y),
                              __float_as_uint(v.z), __float_as_uint(v.w) };
#pragma unroll
            for (int j = 0; j < 4; j++) {
                if ((b[j] >> (shift + 8)) == pfx) {
                    unsigned bin = (b[j] >> shift) & 255u;
                    unsigned act = __activemask();
                    unsigned mk  = __match_any_sync(act, bin);
                    if ((unsigned)(tid & 31) == (unsigned)(__ffs(mk) - 1))
                        atomicAdd(&scnt[bin], (unsigned)__popc(mk));
                }
            }
        }
        __syncthreads();
        if (tid == 0) {
            long long krem = s_krem, above = 0; int d = 255;
            for (; d > 0; --d) {
                if (above + (long long)scnt[d] >= krem) break;
                above += (long long)scnt[d];
            }
            s_krem   = krem - above;
            s_prefix = (pfx << 8) | (unsigned)d;
        }
        __syncthreads();
    }

    // ---- sum of values strictly above threshold T ----
    const unsigned tb = s_prefix;
    double s = 0.0;
#pragma unroll 4
    for (int i = 0; i < SV4; i++) {
        float4 v = base4[tid + i*STH];
        if (__float_as_uint(v.x) > tb) s += (double)v.x;
        if (__float_as_uint(v.y) > tb) s += (double)v.y;
        if (__float_as_uint(v.z) > tb) s += (double)v.z;
        if (__float_as_uint(v.w) > tb) s += (double)v.w;
    }
    double bs = blockReduceD1024(s, sred);

    // ---- global combine + reset (last block) ----
    if (tid == 0) {
        double negrow = bs + (double)s_krem * (double)__uint_as_float(tb);
        atomicAdd(&g_negsum, negrow);
        __threadfence();
        unsigned ticket = atomicAdd(&g_done, 1u);
        if (ticket == BB - 1) {
            __threadfence();
            double tp = 0.0;
            for (int b = 0; b < BB; b++) tp += (double)g_numpos[b];
            out[0] = (float)(20.0 * g_locsum / tp);
            out[1] = (float)((g_posce + g_negsum) / tp);
            // reset state for next graph replay
            for (int b = 0; b < BB; b++) g_numpos[b] = 0;
            g_locsum = 0.0;
            g_posce  = 0.0;
            g_negsum = 0.0;
            __threadfence();
            g_done   = 0u;
        }
    }
}

// ---------------- launch -----------------------------------------------------
extern "C" void kernel_launch(void* const* d_in, const int* in_sizes, int n_in,
                              void* d_out, int out_size) {
    const float* locp = (const float*)d_in[0];
    const float* loct = (const float*)d_in[1];
    const float* cls  = (const float*)d_in[2];
    const int*   tgt  = (const int*)d_in[3];
    float* out = (float*)d_out;

    main_k<<<MAIN_BLOCKS, 256>>>(locp, loct, cls, tgt);
    select_k<<<BB, STH>>>(out);
}

// round 4
// speedup vs baseline: 1.7018x; 1.7018x over previous
#include <cuda_runtime.h>
#include <stdint.h>

#define BB 32
#define AA 65536
#define CC 21
#define NANCH (BB*AA)
#define MAIN_BLOCKS (NANCH/256)
#define PB 32                       // pass blocks per row
#define PASS_BLOCKS (BB*PB)         // 1024
#define FPT 8                       // floats per thread per pass (AA/(PB*256))

// ---------------- scratch (device globals; no allocation allowed) ----------
__device__ float        g_neg[NANCH];        // neg_cand per anchor (8 MB, L2-resident)
__device__ unsigned int g_hist[4][BB*256];   // per-level per-row histograms
__device__ int          g_numpos[BB];
__device__ double       g_locsum;
__device__ double       g_posce;
__device__ double       g_negsum;
__device__ unsigned int g_done;

// ---------------- helpers ---------------------------------------------------
__device__ __forceinline__ double blockReduceD256(double x, double* sred) {
    int lane = threadIdx.x & 31, wid = threadIdx.x >> 5;
#pragma unroll
    for (int o = 16; o; o >>= 1) x += __shfl_down_sync(0xffffffffu, x, o);
    if (lane == 0) sred[wid] = x;
    __syncthreads();
    double r = (wid == 0 && lane < 8) ? sred[lane] : 0.0;
    if (wid == 0) {
#pragma unroll
        for (int o = 4; o; o >>= 1) r += __shfl_down_sync(0xffffffffu, r, o);
    }
    return r;  // valid on thread 0
}

// Block-parallel digit finder: given 256-bin histogram gh and remaining count
// krem, return the radix digit d = max{d : suffix_sum(d) >= krem} and update
// krem -= (suffix_sum(d) - cnt[d]).  256 threads participate.
struct DigitSmem {
    unsigned sS[256];
    unsigned sc[256];
    unsigned swm[8];
    unsigned sdig;
};

__device__ __forceinline__ unsigned find_digit(const unsigned* __restrict__ gh,
                                               long long& krem, DigitSmem* ds) {
    const int tid = threadIdx.x, lane = tid & 31, w = tid >> 5;
    unsigned c = gh[tid];
    unsigned S = c;                 // inclusive suffix sum within warp
#pragma unroll
    for (int off = 1; off < 32; off <<= 1) {
        unsigned t = __shfl_down_sync(0xffffffffu, S, off);
        if (lane + off < 32) S += t;
    }
    if (lane == 0) ds->swm[w] = S;  // warp total
    __syncthreads();
    unsigned add = 0;
#pragma unroll
    for (int ww = 0; ww < 8; ww++) if (ww > w) add += ds->swm[ww];
    S += add;
    ds->sS[tid] = S;
    ds->sc[tid] = c;
    __syncthreads();
    bool p = ((long long)S >= krem);
    unsigned bal = __ballot_sync(0xffffffffu, p);
    __syncthreads();                // protect swm reuse
    if (lane == 0) ds->swm[w] = bal;
    __syncthreads();
    if (tid == 0) {
        int dig = 0;
#pragma unroll
        for (int ww = 7; ww >= 0; --ww) {
            if (ds->swm[ww]) { dig = ww * 32 + (31 - __clz(ds->swm[ww])); break; }
        }
        ds->sdig = (unsigned)dig;
    }
    __syncthreads();
    unsigned d = ds->sdig;
    krem -= (long long)ds->sS[d] - (long long)ds->sc[d];
    return d;
}

__device__ __forceinline__ long long init_krem(int row) {
    long long k = 3LL * (long long)g_numpos[row];
    if (k < 1) k = 1;
    if (k > AA - 1) k = AA - 1;
    return k;
}

// ---------------- main kernel ------------------------------------------------
__global__ void __launch_bounds__(256) main_k(const float* __restrict__ locp,
                                              const float* __restrict__ loct,
                                              const float* __restrict__ cls,
                                              const int* __restrict__ tgt) {
    __shared__ float        scls[256*CC];
    __shared__ unsigned int shist[256];
    __shared__ double       sred[8];

    const int tid    = threadIdx.x;
    const int anchor = blockIdx.x * 256 + tid;
    const int row    = anchor >> 16;

    {
        const float4* src = reinterpret_cast<const float4*>(cls) + (size_t)blockIdx.x * (256*CC/4);
        float4*       dst = reinterpret_cast<float4*>(scls);
#pragma unroll
        for (int i = 0; i < 6; i++) {
            int idx = tid + i * 256;
            if (idx < 256*CC/4) dst[idx] = src[idx];
        }
    }
    shist[tid] = 0u;
    __syncthreads();

    int  t   = tgt[anchor];
    bool pos = (t > 0);

    float v[CC];
#pragma unroll
    for (int c = 0; c < CC; c++) v[c] = scls[tid*CC + c];
    float m = v[0];
#pragma unroll
    for (int c = 1; c < CC; c++) m = fmaxf(m, v[c]);
    float s = 0.f;
#pragma unroll
    for (int c = 0; c < CC; c++) s += __expf(v[c] - m);

    int tc = t; tc = tc < 0 ? 0 : (tc > CC-1 ? CC-1 : tc);
    float picked = scls[tid*CC + tc];
    float ce     = (t == -1) ? 0.f : (m + __logf(s) - picked);
    float negc   = pos ? 0.f : ce;
    g_neg[anchor] = negc;

    float4 p = reinterpret_cast<const float4*>(locp)[anchor];
    float4 q = reinterpret_cast<const float4*>(loct)[anchor];
    float d0 = p.x-q.x, d1 = p.y-q.y, d2 = p.z-q.z, d3 = p.w-q.w;
    float a0 = fabsf(d0), a1 = fabsf(d1), a2 = fabsf(d2), a3 = fabsf(d3);
    float lsum = (a0 < 1.f ? 0.5f*d0*d0 : a0-0.5f)
               + (a1 < 1.f ? 0.5f*d1*d1 : a1-0.5f)
               + (a2 < 1.f ? 0.5f*d2*d2 : a2-0.5f)
               + (a3 < 1.f ? 0.5f*d3*d3 : a3-0.5f);
    if (!pos) lsum = 0.f;

    {
        unsigned bits = __float_as_uint(negc);
        unsigned bin  = bits >> 24;
        unsigned mk   = __match_any_sync(0xffffffffu, bin);
        if ((tid & 31) == (__ffs(mk) - 1))
            atomicAdd(&shist[bin], (unsigned)__popc(mk));
    }

    int npos = __syncthreads_count(pos ? 1 : 0);

    double bl = blockReduceD256((double)lsum, sred);
    __syncthreads();
    double bp = blockReduceD256(pos ? (double)ce : 0.0, sred);

    if (tid == 0) {
        atomicAdd(&g_locsum, bl);
        atomicAdd(&g_posce,  bp);
        atomicAdd(&g_numpos[row], npos);
    }
    if (shist[tid]) atomicAdd(&g_hist[0][row*256 + tid], shist[tid]);
}

// ---------------- per-level histogram pass -----------------------------------
// LEVEL in {1,2,3}. 32 blocks per row; each block recomputes digits 0..LEVEL-1
// from the global level histograms, then histograms its slice at this level.
template <int LEVEL>
__global__ void __launch_bounds__(256) hist_k() {
    __shared__ DigitSmem ds;
    __shared__ unsigned  shist[256];

    const int row = blockIdx.x >> 5;
    const int sub = blockIdx.x & 31;
    const int tid = threadIdx.x;

    long long krem = init_krem(row);
    unsigned pfx = 0;
#pragma unroll
    for (int l = 0; l < LEVEL; l++)
        pfx = (pfx << 8) | find_digit(&g_hist[l][row*256], krem, &ds);

    shist[tid] = 0u;
    __syncthreads();

    const uint4* b4 = reinterpret_cast<const uint4*>(g_neg + (size_t)row*AA + sub*(AA/PB));
    const int pshift = 32 - 8*LEVEL;   // prefix compare shift
    const int bshift = 24 - 8*LEVEL;   // bin extract shift
#pragma unroll
    for (int i = 0; i < FPT/4; i++) {
        uint4 v = b4[tid + i*256];
        unsigned b[4] = { v.x, v.y, v.z, v.w };
#pragma unroll
        for (int j = 0; j < 4; j++) {
            if ((b[j] >> pshift) == pfx) {
                unsigned bin = (b[j] >> bshift) & 255u;
                unsigned act = __activemask();
                unsigned mk  = __match_any_sync(act, bin);
                if ((unsigned)(tid & 31) == (unsigned)(__ffs(mk) - 1))
                    atomicAdd(&shist[bin], (unsigned)__popc(mk));
            }
        }
    }
    __syncthreads();
    if (shist[tid]) atomicAdd(&g_hist[LEVEL][row*256 + tid], shist[tid]);
}

// ---------------- final pass: sum above threshold + combine + reset -----------
__global__ void __launch_bounds__(256) fin_k(float* __restrict__ out) {
    __shared__ DigitSmem ds;
    __shared__ double    sred[8];
    __shared__ int       s_last;

    const int row = blockIdx.x >> 5;
    const int sub = blockIdx.x & 31;
    const int tid = threadIdx.x;

    long long krem = init_krem(row);
    unsigned tb = 0;
#pragma unroll
    for (int l = 0; l < 4; l++)
        tb = (tb << 8) | find_digit(&g_hist[l][row*256], krem, &ds);

    const uint4* b4 = reinterpret_cast<const uint4*>(g_neg + (size_t)row*AA + sub*(AA/PB));
    double s = 0.0;
#pragma unroll
    for (int i = 0; i < FPT/4; i++) {
        uint4 v = b4[tid + i*256];
        if (v.x > tb) s += (double)__uint_as_float(v.x);
        if (v.y > tb) s += (double)__uint_as_float(v.y);
        if (v.z > tb) s += (double)__uint_as_float(v.z);
        if (v.w > tb) s += (double)__uint_as_float(v.w);
    }
    double bs = blockReduceD256(s, sred);

    if (tid == 0) {
        double part = bs;
        if (sub == 0) part += (double)krem * (double)__uint_as_float(tb);
        atomicAdd(&g_negsum, part);
        __threadfence();
        unsigned ticket = atomicAdd(&g_done, 1u);
        s_last = (ticket == PASS_BLOCKS - 1) ? 1 : 0;
    }
    __syncthreads();

    if (s_last) {
        __threadfence();
        // parallel reset of histograms (4 * 8192 words)
        for (int i = tid; i < 4*BB*256; i += 256)
            ((unsigned*)g_hist)[i] = 0u;
        if (tid == 0) {
            double tp = 0.0;
            for (int b = 0; b < BB; b++) { tp += (double)g_numpos[b]; g_numpos[b] = 0; }
            out[0] = (float)(20.0 * g_locsum / tp);
            out[1] = (float)((g_posce + g_negsum) / tp);
            g_locsum = 0.0;
            g_posce  = 0.0;
            g_negsum = 0.0;
            __threadfence();
            g_done = 0u;
        }
    }
}

// ---------------- launch -----------------------------------------------------
extern "C" void kernel_launch(void* const* d_in, const int* in_sizes, int n_in,
                              void* d_out, int out_size) {
    const float* locp = (const float*)d_in[0];
    const float* loct = (const float*)d_in[1];
    const float* cls  = (const float*)d_in[2];
    const int*   tgt  = (const int*)d_in[3];
    float* out = (float*)d_out;

    main_k<<<MAIN_BLOCKS, 256>>>(locp, loct, cls, tgt);
    hist_k<1><<<PASS_BLOCKS, 256>>>();
    hist_k<2><<<PASS_BLOCKS, 256>>>();
    hist_k<3><<<PASS_BLOCKS, 256>>>();
    fin_k<<<PASS_BLOCKS, 256>>>(out);
}

// round 6
// speedup vs baseline: 2.4537x; 1.4418x over previous
#include <cuda_runtime.h>
#include <stdint.h>

#define BB 32
#define AA 65536
#define CC 21
#define NANCH (BB*AA)
#define MAIN_BLOCKS (NANCH/256)
#define CNT_STRIDE 32            // pad per-row counters to separate cache lines

// ---------------- scratch (device globals; no allocation allowed) ----------
__device__ float        g_cand[NANCH];        // compacted nonzero neg CEs per row
__device__ unsigned int g_cnt[BB*CNT_STRIDE]; // per-row nonzero count (padded)
__device__ int          g_numpos[BB];
__device__ double       g_locsum;
__device__ double       g_posce;
__device__ double       g_negsum;
__device__ int          g_tp;                 // total positives across batch
__device__ unsigned int g_done;

// ---------------- helpers ---------------------------------------------------
// Reduce two doubles at once across a 256-thread block. Results valid on tid 0.
__device__ __forceinline__ void blockReduce2(double& x, double& y, double2* sred) {
    int lane = threadIdx.x & 31, wid = threadIdx.x >> 5;
#pragma unroll
    for (int o = 16; o; o >>= 1) {
        x += __shfl_down_sync(0xffffffffu, x, o);
        y += __shfl_down_sync(0xffffffffu, y, o);
    }
    if (lane == 0) sred[wid] = make_double2(x, y);
    __syncthreads();
    if (wid == 0) {
        double2 r = (lane < 8) ? sred[lane] : make_double2(0.0, 0.0);
        double a = r.x, b = r.y;
#pragma unroll
        for (int o = 4; o; o >>= 1) {
            a += __shfl_down_sync(0xffffffffu, a, o);
            b += __shfl_down_sync(0xffffffffu, b, o);
        }
        x = a; y = b;
    }
}

struct DigitSmem {
    unsigned sS[256];
    unsigned sc[256];
    unsigned swm[8];
    unsigned sdig;
};

// Block-parallel (256 threads) digit finder over a 256-bin shared histogram.
__device__ __forceinline__ unsigned find_digit(const unsigned* __restrict__ hist,
                                               long long& krem, DigitSmem* ds) {
    const int tid = threadIdx.x, lane = tid & 31, w = tid >> 5;
    unsigned c = hist[tid];
    unsigned S = c;
#pragma unroll
    for (int off = 1; off < 32; off <<= 1) {
        unsigned t = __shfl_down_sync(0xffffffffu, S, off);
        if (lane + off < 32) S += t;
    }
    if (lane == 0) ds->swm[w] = S;
    __syncthreads();
    unsigned add = 0;
#pragma unroll
    for (int ww = 0; ww < 8; ww++) if (ww > w) add += ds->swm[ww];
    S += add;
    ds->sS[tid] = S;
    ds->sc[tid] = c;
    __syncthreads();
    bool p = ((long long)S >= krem);
    unsigned bal = __ballot_sync(0xffffffffu, p);
    __syncthreads();
    if (lane == 0) ds->swm[w] = bal;
    __syncthreads();
    if (tid == 0) {
        int dig = 0;
#pragma unroll
        for (int ww = 7; ww >= 0; --ww) {
            if (ds->swm[ww]) { dig = ww * 32 + (31 - __clz(ds->swm[ww])); break; }
        }
        ds->sdig = (unsigned)dig;
    }
    __syncthreads();
    unsigned d = ds->sdig;
    krem -= (long long)ds->sS[d] - (long long)ds->sc[d];
    return d;
}

// ---------------- main kernel ------------------------------------------------
__global__ void __launch_bounds__(256) main_k(const float* __restrict__ locp,
                                              const float* __restrict__ loct,
                                              const float* __restrict__ cls,
                                              const int* __restrict__ tgt) {
    __shared__ float   scls[256*CC];
    __shared__ double2 sred[8];

    const int tid    = threadIdx.x;
    const int lane   = tid & 31;
    const int anchor = blockIdx.x * 256 + tid;
    const int row    = anchor >> 16;          // uniform per block

    // stage cls tile (coalesced float4)
    {
        const float4* src = reinterpret_cast<const float4*>(cls) + (size_t)blockIdx.x * (256*CC/4);
        float4*       dst = reinterpret_cast<float4*>(scls);
#pragma unroll
        for (int i = 0; i < 6; i++) {
            int idx = tid + i * 256;
            if (idx < 256*CC/4) dst[idx] = src[idx];
        }
    }
    __syncthreads();

    int  t   = tgt[anchor];
    bool pos = (t > 0);

    // logsumexp over 21 classes (stride-21 LDS is bank-conflict-free)
    float v[CC];
#pragma unroll
    for (int c = 0; c < CC; c++) v[c] = scls[tid*CC + c];
    float m = v[0];
#pragma unroll
    for (int c = 1; c < CC; c++) m = fmaxf(m, v[c]);
    float s = 0.f;
#pragma unroll
    for (int c = 0; c < CC; c++) s += __expf(v[c] - m);

    int tc = t; tc = tc < 0 ? 0 : (tc > CC-1 ? CC-1 : tc);
    float picked = scls[tid*CC + tc];
    float ce     = (t == -1) ? 0.f : (m + __logf(s) - picked);
    float negc   = pos ? 0.f : ce;

    // compact nonzero negatives (warp-aggregated)
    {
        unsigned bits = __float_as_uint(negc);
        unsigned mkz  = __ballot_sync(0xffffffffu, bits != 0u);
        if (mkz) {
            int leader = __ffs(mkz) - 1;
            unsigned base = 0;
            if (lane == leader) base = atomicAdd(&g_cnt[row*CNT_STRIDE], (unsigned)__popc(mkz));
            base = __shfl_sync(0xffffffffu, base, leader);
            if (bits != 0u) {
                unsigned off = (unsigned)__popc(mkz & ((1u << lane) - 1u));
                g_cand[(size_t)row*AA + base + off] = negc;
            }
        }
    }

    // smooth-L1 (unconditional loads; masked result)
    float4 p = reinterpret_cast<const float4*>(locp)[anchor];
    float4 q = reinterpret_cast<const float4*>(loct)[anchor];
    float d0 = p.x-q.x, d1 = p.y-q.y, d2 = p.z-q.z, d3 = p.w-q.w;
    float a0 = fabsf(d0), a1 = fabsf(d1), a2 = fabsf(d2), a3 = fabsf(d3);
    float lsum = (a0 < 1.f ? 0.5f*d0*d0 : a0-0.5f)
               + (a1 < 1.f ? 0.5f*d1*d1 : a1-0.5f)
               + (a2 < 1.f ? 0.5f*d2*d2 : a2-0.5f)
               + (a3 < 1.f ? 0.5f*d3*d3 : a3-0.5f);
    if (!pos) lsum = 0.f;

    int npos = __syncthreads_count(pos ? 1 : 0);

    double bl = (double)lsum;
    double bp = pos ? (double)ce : 0.0;
    blockReduce2(bl, bp, sred);

    if (tid == 0) {
        atomicAdd(&g_locsum, bl);
        atomicAdd(&g_posce,  bp);
        atomicAdd(&g_numpos[row], npos);
    }
}

// ---------------- tiny per-row select on compacted list ----------------------
__global__ void __launch_bounds__(256) select_k(float* __restrict__ out) {
    __shared__ DigitSmem ds;
    __shared__ unsigned  shist[256];
    __shared__ double2   sred[8];
    __shared__ int       s_last;

    const int row = blockIdx.x;
    const int tid = threadIdx.x;

    const int n    = (int)g_cnt[row*CNT_STRIDE];
    const int npos = g_numpos[row];
    long long k = 3LL * (long long)npos;
    if (k < 1) k = 1;
    if (k > AA-1) k = AA-1;

    const float* cand = g_cand + (size_t)row*AA;

    // pass 1: total sum + level-0 histogram
    shist[tid] = 0u;
    __syncthreads();
    double tot = 0.0;
    for (int i = tid; i < n; i += 256) {
        float f = cand[i];
        tot += (double)f;
        atomicAdd(&shist[__float_as_uint(f) >> 24], 1u);
    }
    __syncthreads();
    {
        double dummy = 0.0;
        blockReduce2(tot, dummy, sred);   // tot now valid on tid 0
    }
    __syncthreads();

    double negrow;
    if (k >= (long long)n) {
        negrow = tot;                     // all nonzeros selected; ties are zeros (tid 0 valid)
    } else {
        long long krem = k;
        unsigned pfx = find_digit(shist, krem, &ds);
        // levels 1..3
#pragma unroll
        for (int shift = 16; shift >= 0; shift -= 8) {
            __syncthreads();
            shist[tid] = 0u;
            __syncthreads();
            for (int i = tid; i < n; i += 256) {
                unsigned b = __float_as_uint(cand[i]);
                if ((b >> (shift + 8)) == pfx)
                    atomicAdd(&shist[(b >> shift) & 255u], 1u);
            }
            __syncthreads();
            pfx = (pfx << 8) | find_digit(shist, krem, &ds);
        }
        const unsigned tb = pfx;
        double sgt = 0.0, dummy = 0.0;
        for (int i = tid; i < n; i += 256) {
            unsigned b = __float_as_uint(cand[i]);
            if (b > tb) sgt += (double)__uint_as_float(b);
        }
        blockReduce2(sgt, dummy, sred);
        negrow = sgt + (double)krem * (double)__uint_as_float(tb);
    }

    // per-row state reset for next graph replay
    if (tid == 0) {
        g_cnt[row*CNT_STRIDE] = 0u;
        g_numpos[row] = 0;
        atomicAdd(&g_negsum, negrow);
        atomicAdd(&g_tp, npos);
        __threadfence();
        unsigned ticket = atomicAdd(&g_done, 1u);
        s_last = (ticket == BB - 1) ? 1 : 0;
    }
    __syncthreads();

    if (s_last && tid == 0) {
        __threadfence();
        double tp = (double)g_tp;
        out[0] = (float)(20.0 * g_locsum / tp);
        out[1] = (float)((g_posce + g_negsum) / tp);
        g_locsum = 0.0;
        g_posce  = 0.0;
        g_negsum = 0.0;
        g_tp     = 0;
        __threadfence();
        g_done   = 0u;
    }
}

// ---------------- launch -----------------------------------------------------
extern "C" void kernel_launch(void* const* d_in, const int* in_sizes, int n_in,
                              void* d_out, int out_size) {
    const float* locp = (const float*)d_in[0];
    const float* loct = (const float*)d_in[1];
    const float* cls  = (const float*)d_in[2];
    const int*   tgt  = (const int*)d_in[3];
    float* out = (float*)d_out;

    main_k<<<MAIN_BLOCKS, 256>>>(locp, loct, cls, tgt);
    select_k<<<BB, 256>>>(out);
}